// round 7
// baseline (speedup 1.0000x reference)
#include <cuda_runtime.h>
#include <cstdint>

#define B_N   16384
#define K_N   2048
#define F_N   1024
#define H_N   1024
#define D_N   3
#define TOPK  8
#define NCAND 16
#define LN_EPS 1e-5f

// ---------------- scratch (static device globals; no runtime allocation) ---
__device__ float g_fn  [(size_t)B_N * F_N];   // normalized features (fp32, exact)
__device__ float g_gn  [(size_t)K_N * F_N];   // normalized graphone (fp32, exact)
__device__ float g_fnr [(size_t)B_N * F_N];   // tf32-rounded fn (for approx sim)
__device__ float g_gnr [(size_t)K_N * F_N];   // tf32-rounded gn
__device__ float g_sim [(size_t)B_N * K_N];   // APPROX similarity (1xTF32)
__device__ float g_aggp[(size_t)B_N * F_N];   // max over top-8 graphone rows (tf32)
__device__ float g_x   [(size_t)B_N * F_N];   // depth-loop activations (tf32)
__device__ float g_am  [(size_t)B_N * F_N];   // max(aggp, x) (tf32)
__device__ float g_h   [(size_t)B_N * H_N];   // hidden
__device__ float g_wl  [(size_t)D_N * H_N * F_N];  // tf32-rounded weights
__device__ float g_wr  [(size_t)D_N * H_N * F_N];
__device__ float g_wp  [(size_t)D_N * F_N * H_N];

// ---------------- small PTX helpers ----------------------------------------
__device__ __forceinline__ float tf32r(float x) {
    float r;
    asm("cvt.rna.tf32.f32 %0, %1;" : "=f"(r) : "f"(x));
    return r;
}
__device__ __forceinline__ void ldsm4(uint32_t& r0, uint32_t& r1,
                                      uint32_t& r2, uint32_t& r3, uint32_t a) {
    asm volatile("ldmatrix.sync.aligned.m8n8.x4.shared.b16 {%0,%1,%2,%3}, [%4];"
                 : "=r"(r0), "=r"(r1), "=r"(r2), "=r"(r3) : "r"(a));
}
__device__ __forceinline__ void mma_tf32(float c[4],
                                         uint32_t a0, uint32_t a1, uint32_t a2, uint32_t a3,
                                         uint32_t b0, uint32_t b1) {
    asm volatile("mma.sync.aligned.m16n8k8.row.col.f32.tf32.tf32.f32 "
                 "{%0,%1,%2,%3},{%4,%5,%6,%7},{%8,%9},{%0,%1,%2,%3};"
                 : "+f"(c[0]), "+f"(c[1]), "+f"(c[2]), "+f"(c[3])
                 : "r"(a0), "r"(a1), "r"(a2), "r"(a3), "r"(b0), "r"(b1));
}
__device__ __forceinline__ void cpasync16(uint32_t dst, const void* src) {
    asm volatile("cp.async.cg.shared.global [%0], [%1], 16;" :: "r"(dst), "l"(src));
}
__device__ __forceinline__ void cp_commit() {
    asm volatile("cp.async.commit_group;");
}
__device__ __forceinline__ void cp_wait0() {
    asm volatile("cp.async.wait_group 0;");
}
__device__ __forceinline__ void cp_wait1() {
    asm volatile("cp.async.wait_group 1;");
}

// ---------------- row L2 normalize; writes exact + tf32-rounded copies -----
__global__ void normalize_rows(const float* __restrict__ feat,
                               const float* __restrict__ gr) {
    int row = blockIdx.x;
    const float* src;
    float* dst; float* dstr;
    if (row < B_N) {
        src = feat + (size_t)row * F_N;
        dst = g_fn + (size_t)row * F_N;  dstr = g_fnr + (size_t)row * F_N;
    } else {
        row -= B_N;
        src = gr + (size_t)row * F_N;
        dst = g_gn + (size_t)row * F_N;  dstr = g_gnr + (size_t)row * F_N;
    }
    int t = threadIdx.x;
    float4 v = ((const float4*)src)[t];
    float ss = v.x*v.x + v.y*v.y + v.z*v.z + v.w*v.w;
    __shared__ float red[8];
    #pragma unroll
    for (int o = 16; o > 0; o >>= 1) ss += __shfl_xor_sync(0xffffffffu, ss, o);
    if ((t & 31) == 0) red[t >> 5] = ss;
    __syncthreads();
    if (t == 0) {
        float s = 0.f;
        #pragma unroll
        for (int i = 0; i < 8; i++) s += red[i];
        red[0] = s;
    }
    __syncthreads();
    float inv = rsqrtf(red[0]);
    v.x *= inv; v.y *= inv; v.z *= inv; v.w *= inv;
    ((float4*)dst)[t] = v;
    float4 r4;
    r4.x = tf32r(v.x); r4.y = tf32r(v.y); r4.z = tf32r(v.z); r4.w = tf32r(v.w);
    ((float4*)dstr)[t] = r4;
}

// ---------------- TF32 tensor-core NT GEMM (pre-rounded operands) ----------
// 3-stage cp.async pipeline.
// MODE 1: dual phase (Kd = 2F): k<F uses (A0,B0), k>=F uses (A1,B1), lda=F
// MODE 2: single (A0,B0)
// EPI 0: store raw            (SAGE h / approx sim)
// EPI 1: +bias, round tf32, also Am = max(aggp, x)   (intermediate proj)
// EPI 2: +bias, store raw to out                     (final proj)
template <int MODE, int EPI>
__global__ void __launch_bounds__(256, 2)
tgemm(const float* __restrict__ A0, const float* __restrict__ A1,
      const float* __restrict__ B0p, const float* __restrict__ B1p,
      const float* __restrict__ bias, const float* __restrict__ aggp,
      float* __restrict__ C, float* __restrict__ Am,
      int M, int N, int Kd) {
    const int BM = 128, BN = 128, BK = 16, NS = 3;
    __shared__ float As[NS][BM * BK];
    __shared__ float Bs[NS][BM * BK];

    const int tid  = threadIdx.x;
    const int lane = tid & 31;
    const int warp = tid >> 5;
    const int wm = warp >> 2;
    const int wn = warp & 3;
    const int g  = lane >> 3;
    const int li = lane & 7;
    const int m0 = blockIdx.y * BM;
    const int n0 = blockIdx.x * BN;

    const uint32_t sA = (uint32_t)__cvta_generic_to_shared(&As[0][0]);
    const uint32_t sB = (uint32_t)__cvta_generic_to_shared(&Bs[0][0]);

    float acc[4][4][4];
    #pragma unroll
    for (int a = 0; a < 4; a++)
        #pragma unroll
        for (int b = 0; b < 4; b++)
            #pragma unroll
            for (int c = 0; c < 4; c++) acc[a][b][c] = 0.f;

    const int halfK = Kd >> 1;
    const int NT = Kd / BK;

    auto issue_loads = [&](int kt) {
        int kk = kt * BK;
        int buf = kt % NS;
        const float* Aptr; const float* Bptr; int kb = kk; int ld;
        if (MODE == 1) {
            ld = halfK;
            if (kk >= halfK) { Aptr = A1; Bptr = B1p; kb = kk - halfK; }
            else             { Aptr = A0; Bptr = B0p; }
        } else {
            ld = Kd; Aptr = A0; Bptr = B0p;
        }
        #pragma unroll
        for (int it = 0; it < 2; it++) {
            int f = tid + it * 256;
            int r = f >> 2, c4 = f & 3;
            uint32_t soff = (uint32_t)(buf * BM * BK + r * BK + ((c4 ^ ((r >> 1) & 3)) << 2)) * 4u;
            cpasync16(sA + soff, Aptr + (size_t)(m0 + r) * ld + kb + c4 * 4);
            cpasync16(sB + soff, Bptr + (size_t)(n0 + r) * ld + kb + c4 * 4);
        }
        cp_commit();
    };

    issue_loads(0);
    issue_loads(1);

    for (int kt = 0; kt < NT; kt++) {
        if (kt + 1 < NT) cp_wait1(); else cp_wait0();
        __syncthreads();
        if (kt + 2 < NT) issue_loads(kt + 2);

        const uint32_t baseA = sA + (uint32_t)((kt % NS) * BM * BK) * 4u;
        const uint32_t baseB = sB + (uint32_t)((kt % NS) * BM * BK) * 4u;

        #pragma unroll
        for (int s = 0; s < 2; s++) {
            uint32_t a[4][4];
            #pragma unroll
            for (int mi = 0; mi < 4; mi++) {
                int row = wm * 64 + mi * 16 + ((g & 1) << 3) + li;
                int ch  = (2 * s + (g >> 1)) ^ ((row >> 1) & 3);
                ldsm4(a[mi][0], a[mi][1], a[mi][2], a[mi][3],
                      baseA + (uint32_t)((row * BK + (ch << 2)) << 2));
            }
            uint32_t b[4][2];
            #pragma unroll
            for (int p = 0; p < 2; p++) {
                int row = wn * 32 + p * 16 + ((g >> 1) << 3) + li;
                int ch  = (2 * s + (g & 1)) ^ ((row >> 1) & 3);
                uint32_t r0, r1, r2, r3;
                ldsm4(r0, r1, r2, r3,
                      baseB + (uint32_t)((row * BK + (ch << 2)) << 2));
                b[2*p][0] = r0; b[2*p][1] = r1;
                b[2*p+1][0] = r2; b[2*p+1][1] = r3;
            }
            #pragma unroll
            for (int mi = 0; mi < 4; mi++)
                #pragma unroll
                for (int nj = 0; nj < 4; nj++)
                    mma_tf32(acc[mi][nj], a[mi][0], a[mi][1], a[mi][2], a[mi][3],
                             b[nj][0], b[nj][1]);
        }
    }

    #pragma unroll
    for (int mi = 0; mi < 4; mi++) {
        #pragma unroll
        for (int half = 0; half < 2; half++) {
            int row = m0 + wm * 64 + mi * 16 + (lane >> 2) + half * 8;
            #pragma unroll
            for (int nj = 0; nj < 4; nj++) {
                int col = n0 + wn * 32 + nj * 8 + ((lane & 3) << 1);
                float v0 = acc[mi][nj][half * 2 + 0];
                float v1 = acc[mi][nj][half * 2 + 1];
                size_t idx = (size_t)row * N + col;
                if (EPI >= 1) { v0 += bias[col]; v1 += bias[col + 1]; }
                if (EPI == 1) {
                    v0 = tf32r(v0); v1 = tf32r(v1);
                    Am[idx]     = fmaxf(aggp[idx],     v0);
                    Am[idx + 1] = fmaxf(aggp[idx + 1], v1);
                }
                C[idx] = v0; C[idx + 1] = v1;
            }
        }
    }
}

// ---------------- fused topk + exact rescore + aggproto ---------------------
// Phase A: each warp holds 256 sim values in registers, extracts local top-16
//          with pure shuffle reductions (no barriers).
// Phase B: warp 0 merges 8x16 = 128 candidates -> block top-16 (no barriers).
// Phase C: exact fp32 rescore of 16 candidates -> top-8 (matches jax order).
// Phase D: aggp = max over top-8 graphone rows; x0 = tf32(features);
//          am0 = max(aggp, x0)   (fused, uses sel[] in smem).
__global__ void topk_kernel(const float* __restrict__ graphone,
                            const float* __restrict__ features,
                            float* __restrict__ out, int write_assign) {
    int b = blockIdx.x;
    int t = threadIdx.x;                      // 256 threads
    int lane = t & 31, w = t >> 5;
    __shared__ float fnrow[F_N];              // exact fn row
    __shared__ float cvals[8 * NCAND];        // per-warp candidate values
    __shared__ int   cidx [8 * NCAND];        // per-warp candidate indices
    __shared__ int   cand[NCAND];
    __shared__ float exacts[NCAND];
    __shared__ int   sel[TOPK];

    ((float4*)fnrow)[t] = ((const float4*)(g_fn + (size_t)b * F_N))[t];

    // ---- Phase A: per-warp top-16 of its 256 contiguous elements ----------
    const float* row = g_sim + (size_t)b * K_N;
    int base = w * 256 + lane * 8;
    float v[8];
    {
        float4 a0 = *(const float4*)(row + base);
        float4 a1 = *(const float4*)(row + base + 4);
        v[0]=a0.x; v[1]=a0.y; v[2]=a0.z; v[3]=a0.w;
        v[4]=a1.x; v[5]=a1.y; v[6]=a1.z; v[7]=a1.w;
    }
    float lmax = -3.0e38f; int le = 0;
    #pragma unroll
    for (int e = 0; e < 8; e++) if (v[e] > lmax) { lmax = v[e]; le = e; }

    for (int r = 0; r < NCAND; r++) {
        float bv = lmax; int bi = lane * 8 + le;   // index within warp chunk
        #pragma unroll
        for (int o = 16; o > 0; o >>= 1) {
            float ov = __shfl_xor_sync(0xffffffffu, bv, o);
            int   oi = __shfl_xor_sync(0xffffffffu, bi, o);
            if (ov > bv) { bv = ov; bi = oi; }
        }
        if (lane == 0) { cvals[w * NCAND + r] = bv; cidx[w * NCAND + r] = w * 256 + bi; }
        if ((bi >> 3) == lane) {                   // owner invalidates + rescans
            v[bi & 7] = -3.0e38f;
            lmax = -3.0e38f; le = 0;
            #pragma unroll
            for (int e = 0; e < 8; e++) if (v[e] > lmax) { lmax = v[e]; le = e; }
        }
    }
    __syncthreads();

    // ---- Phase B: warp 0 merges 128 candidates -> block top-16 ------------
    if (w == 0) {
        float mv[4];
        #pragma unroll
        for (int q = 0; q < 4; q++) mv[q] = cvals[lane * 4 + q];
        float lm = -3.0e38f; int lq = 0;
        #pragma unroll
        for (int q = 0; q < 4; q++) if (mv[q] > lm) { lm = mv[q]; lq = q; }
        for (int r = 0; r < NCAND; r++) {
            float bv = lm; int slot = lane * 4 + lq;
            #pragma unroll
            for (int o = 16; o > 0; o >>= 1) {
                float ov = __shfl_xor_sync(0xffffffffu, bv, o);
                int   os = __shfl_xor_sync(0xffffffffu, slot, o);
                if (ov > bv) { bv = ov; slot = os; }
            }
            if (lane == 0) cand[r] = cidx[slot];
            if ((slot >> 2) == lane) {
                mv[slot & 3] = -3.0e38f;
                lm = -3.0e38f; lq = 0;
                #pragma unroll
                for (int q = 0; q < 4; q++) if (mv[q] > lm) { lm = mv[q]; lq = q; }
            }
        }
    }
    __syncthreads();

    // ---- Phase C: exact fp32 rescore; warp w handles candidates 2w, 2w+1 --
    #pragma unroll
    for (int q = 0; q < 2; q++) {
        int c = w * 2 + q;
        const float* gp = g_gn + (size_t)cand[c] * F_N;
        float s = 0.f;
        #pragma unroll
        for (int e = 0; e < F_N / 32; e++)
            s = fmaf(fnrow[e * 32 + lane], gp[e * 32 + lane], s);
        #pragma unroll
        for (int o = 16; o > 0; o >>= 1) s += __shfl_xor_sync(0xffffffffu, s, o);
        if (lane == 0) exacts[c] = s;
    }
    __syncthreads();

    // top-8 of the 16 exact values (tie -> lower prototype index, matches jax)
    if (t == 0) {
        float ev[NCAND]; int ci[NCAND];
        #pragma unroll
        for (int i = 0; i < NCAND; i++) { ev[i] = exacts[i]; ci[i] = cand[i]; }
        #pragma unroll
        for (int r = 0; r < TOPK; r++) {
            int bj = 0;
            #pragma unroll
            for (int i = 1; i < NCAND; i++) {
                if (ev[i] > ev[bj] || (ev[i] == ev[bj] && ci[i] < ci[bj])) bj = i;
            }
            sel[r] = ci[bj];
            if (r == 0 && write_assign) {
                #pragma unroll
                for (int dd = 0; dd < D_N; dd++)
                    out[(size_t)B_N * F_N + (size_t)dd * B_N + b] = (float)ci[bj];
            }
            ev[bj] = -3.0e38f;
        }
    }
    __syncthreads();

    // ---- Phase D: fused aggproto -------------------------------------------
    float4 m = ((const float4*)(graphone + (size_t)sel[0] * F_N))[t];
    #pragma unroll
    for (int j = 1; j < TOPK; j++) {
        float4 vv = ((const float4*)(graphone + (size_t)sel[j] * F_N))[t];
        m.x = fmaxf(m.x, vv.x); m.y = fmaxf(m.y, vv.y);
        m.z = fmaxf(m.z, vv.z); m.w = fmaxf(m.w, vv.w);
    }
    m.x = tf32r(m.x); m.y = tf32r(m.y); m.z = tf32r(m.z); m.w = tf32r(m.w);
    ((float4*)(g_aggp + (size_t)b * F_N))[t] = m;
    float4 f = ((const float4*)(features + (size_t)b * F_N))[t];
    f.x = tf32r(f.x); f.y = tf32r(f.y); f.z = tf32r(f.z); f.w = tf32r(f.w);
    ((float4*)(g_x + (size_t)b * F_N))[t] = f;
    float4 a;
    a.x = fmaxf(m.x, f.x); a.y = fmaxf(m.y, f.y);
    a.z = fmaxf(m.z, f.z); a.w = fmaxf(m.w, f.w);
    ((float4*)(g_am + (size_t)b * F_N))[t] = a;
}

// ---------------- tf32 rounding copy: all three weight tensors, one launch --
__global__ void convert_tf32_all(const float* __restrict__ W_l,
                                 const float* __restrict__ W_r,
                                 const float* __restrict__ W_p, int n4) {
    int i = blockIdx.x * blockDim.x + threadIdx.x;
    if (i >= 3 * n4) return;
    const float* src; float* dst; int j;
    if (i < n4)            { src = W_l; dst = g_wl; j = i; }
    else if (i < 2 * n4)   { src = W_r; dst = g_wr; j = i - n4; }
    else                   { src = W_p; dst = g_wp; j = i - 2 * n4; }
    float4 v = ((const float4*)src)[j];
    v.x = tf32r(v.x); v.y = tf32r(v.y); v.z = tf32r(v.z); v.w = tf32r(v.w);
    ((float4*)dst)[j] = v;
}

// ---------------- LayerNorm + ReLU + tf32 round, in place on g_h -----------
__global__ void ln_relu_kernel(const float* __restrict__ gamma,
                               const float* __restrict__ beta) {
    int b = blockIdx.x;
    int t = threadIdx.x;
    float* row = g_h + (size_t)b * H_N;
    float4 v = ((float4*)row)[t];
    float s  = v.x + v.y + v.z + v.w;
    float ss = v.x*v.x + v.y*v.y + v.z*v.z + v.w*v.w;
    __shared__ float r1[8], r2[8];
    #pragma unroll
    for (int o = 16; o > 0; o >>= 1) {
        s  += __shfl_xor_sync(0xffffffffu, s,  o);
        ss += __shfl_xor_sync(0xffffffffu, ss, o);
    }
    if ((t & 31) == 0) { r1[t >> 5] = s; r2[t >> 5] = ss; }
    __syncthreads();
    if (t == 0) {
        float a = 0.f, c = 0.f;
        #pragma unroll
        for (int i = 0; i < 8; i++) { a += r1[i]; c += r2[i]; }
        r1[0] = a; r2[0] = c;
    }
    __syncthreads();
    float mu  = r1[0] * (1.0f / H_N);
    float var = r2[0] * (1.0f / H_N) - mu * mu;
    float inv = rsqrtf(var + LN_EPS);
    float4 gm = ((const float4*)gamma)[t];
    float4 be = ((const float4*)beta)[t];
    v.x = tf32r(fmaxf((v.x - mu) * inv * gm.x + be.x, 0.f));
    v.y = tf32r(fmaxf((v.y - mu) * inv * gm.y + be.y, 0.f));
    v.z = tf32r(fmaxf((v.z - mu) * inv * gm.z + be.z, 0.f));
    v.w = tf32r(fmaxf((v.w - mu) * inv * gm.w + be.w, 0.f));
    ((float4*)row)[t] = v;
}

// ---------------------------------------------------------------------------
extern "C" void kernel_launch(void* const* d_in, const int* in_sizes, int n_in,
                              void* d_out, int out_size) {
    const float* features = (const float*)d_in[0];
    const float* graphone = (const float*)d_in[1];
    const float* W_l      = (const float*)d_in[2];
    const float* W_r      = (const float*)d_in[3];
    const float* gamma    = (const float*)d_in[4];
    const float* beta     = (const float*)d_in[5];
    const float* W_p      = (const float*)d_in[6];
    const float* b_p      = (const float*)d_in[7];
    float* out = (float*)d_out;

    float *fnr, *gnr, *sim, *aggp, *x, *h, *am, *wl, *wr, *wp;
    cudaGetSymbolAddress((void**)&fnr,  g_fnr);
    cudaGetSymbolAddress((void**)&gnr,  g_gnr);
    cudaGetSymbolAddress((void**)&sim,  g_sim);
    cudaGetSymbolAddress((void**)&aggp, g_aggp);
    cudaGetSymbolAddress((void**)&x,    g_x);
    cudaGetSymbolAddress((void**)&h,    g_h);
    cudaGetSymbolAddress((void**)&am,   g_am);
    cudaGetSymbolAddress((void**)&wl,   g_wl);
    cudaGetSymbolAddress((void**)&wr,   g_wr);
    cudaGetSymbolAddress((void**)&wp,   g_wp);

    // 0) tf32-round all weights (single launch)
    int nW = D_N * H_N * F_N / 4;
    convert_tf32_all<<<(3 * nW + 255) / 256, 256>>>(W_l, W_r, W_p, nW);

    // 1) row normalization -> exact (rescore) + tf32-rounded (approx sim)
    normalize_rows<<<B_N + K_N, 256>>>(features, graphone);

    // 2) APPROX sim = fnr @ gnr^T  (plain TF32 TC GEMM, no in-loop cvt)
    tgemm<2, 0><<<dim3(K_N / 128, B_N / 128), 256>>>(
        fnr, nullptr, gnr, nullptr, nullptr, nullptr, sim, nullptr,
        B_N, K_N, F_N);

    // 3) fused: top-16 candidates -> exact rescore -> top-8 -> aggproto
    long long need = (long long)B_N * F_N + (long long)D_N * B_N;
    int write_assign = ((long long)out_size >= need) ? 1 : 0;
    topk_kernel<<<B_N, 256>>>(graphone, features, out, write_assign);

    // 4) depth loop — tensor-core TF32 GEMMs
    for (int d = 0; d < D_N; d++) {
        // h = am @ W_l[d]^T + x @ W_r[d]^T  (dual-phase, Kd = 2F)
        tgemm<1, 0><<<dim3(H_N / 128, B_N / 128), 256>>>(
            am, x,
            wl + (size_t)d * H_N * F_N, wr + (size_t)d * H_N * F_N,
            nullptr, nullptr, h, nullptr, B_N, H_N, 2 * F_N);

        // LayerNorm + ReLU (+ tf32 rounding of h)
        ln_relu_kernel<<<B_N, 256>>>(gamma + (size_t)d * H_N,
                                     beta  + (size_t)d * H_N);

        if (d < D_N - 1) {
            // x = h @ W_p[d]^T + b_p ; also am = max(aggp, x) fused
            tgemm<2, 1><<<dim3(F_N / 128, B_N / 128), 256>>>(
                h, nullptr, wp + (size_t)d * F_N * H_N, nullptr,
                b_p + (size_t)d * F_N, aggp, x, am, B_N, F_N, H_N);
        } else {
            // final projection straight to d_out, full fp32 epilogue
            tgemm<2, 2><<<dim3(F_N / 128, B_N / 128), 256>>>(
                h, nullptr, wp + (size_t)d * F_N * H_N, nullptr,
                b_p + (size_t)d * F_N, nullptr, out, nullptr, B_N, F_N, H_N);
        }
    }
}

// round 8
// speedup vs baseline: 1.0322x; 1.0322x over previous
#include <cuda_runtime.h>
#include <cstdint>

#define B_N   16384
#define K_N   2048
#define F_N   1024
#define H_N   1024
#define D_N   3
#define TOPK  8
#define NCAND 16
#define LN_EPS 1e-5f

// ---------------- scratch (static device globals; no runtime allocation) ---
__device__ float g_fn  [(size_t)B_N * F_N];   // normalized features (fp32, exact)
__device__ float g_gn  [(size_t)K_N * F_N];   // normalized graphone (fp32, exact)
__device__ float g_fnr [(size_t)B_N * F_N];   // tf32-rounded fn (for approx sim)
__device__ float g_gnr [(size_t)K_N * F_N];   // tf32-rounded gn
__device__ float g_sim [(size_t)B_N * K_N];   // APPROX similarity (1xTF32)
__device__ int   g_topk[(size_t)B_N * TOPK];  // top-8 prototype idx per row
__device__ float g_aggp[(size_t)B_N * F_N];   // max over top-8 graphone rows (tf32)
__device__ float g_x   [(size_t)B_N * F_N];   // depth-loop activations (tf32)
__device__ float g_am  [(size_t)B_N * F_N];   // max(aggp, x) (tf32)
__device__ float g_h   [(size_t)B_N * H_N];   // hidden
__device__ float g_wl  [(size_t)D_N * H_N * F_N];  // tf32-rounded weights
__device__ float g_wr  [(size_t)D_N * H_N * F_N];
__device__ float g_wp  [(size_t)D_N * F_N * H_N];

// ---------------- small PTX helpers ----------------------------------------
__device__ __forceinline__ float tf32r(float x) {
    float r;
    asm("cvt.rna.tf32.f32 %0, %1;" : "=f"(r) : "f"(x));
    return r;
}
__device__ __forceinline__ void ldsm4(uint32_t& r0, uint32_t& r1,
                                      uint32_t& r2, uint32_t& r3, uint32_t a) {
    asm volatile("ldmatrix.sync.aligned.m8n8.x4.shared.b16 {%0,%1,%2,%3}, [%4];"
                 : "=r"(r0), "=r"(r1), "=r"(r2), "=r"(r3) : "r"(a));
}
__device__ __forceinline__ void mma_tf32(float c[4],
                                         uint32_t a0, uint32_t a1, uint32_t a2, uint32_t a3,
                                         uint32_t b0, uint32_t b1) {
    asm volatile("mma.sync.aligned.m16n8k8.row.col.f32.tf32.tf32.f32 "
                 "{%0,%1,%2,%3},{%4,%5,%6,%7},{%8,%9},{%0,%1,%2,%3};"
                 : "+f"(c[0]), "+f"(c[1]), "+f"(c[2]), "+f"(c[3])
                 : "r"(a0), "r"(a1), "r"(a2), "r"(a3), "r"(b0), "r"(b1));
}
__device__ __forceinline__ void cpasync16(uint32_t dst, const void* src) {
    asm volatile("cp.async.cg.shared.global [%0], [%1], 16;" :: "r"(dst), "l"(src));
}
__device__ __forceinline__ void cp_commit() {
    asm volatile("cp.async.commit_group;");
}
__device__ __forceinline__ void cp_wait0() {
    asm volatile("cp.async.wait_group 0;");
}
__device__ __forceinline__ void cp_wait1() {
    asm volatile("cp.async.wait_group 1;");
}

// ---------------- row L2 normalize; writes exact + tf32-rounded copies -----
__global__ void normalize_rows(const float* __restrict__ feat,
                               const float* __restrict__ gr) {
    int row = blockIdx.x;
    const float* src;
    float* dst; float* dstr;
    if (row < B_N) {
        src = feat + (size_t)row * F_N;
        dst = g_fn + (size_t)row * F_N;  dstr = g_fnr + (size_t)row * F_N;
    } else {
        row -= B_N;
        src = gr + (size_t)row * F_N;
        dst = g_gn + (size_t)row * F_N;  dstr = g_gnr + (size_t)row * F_N;
    }
    int t = threadIdx.x;
    float4 v = ((const float4*)src)[t];
    float ss = v.x*v.x + v.y*v.y + v.z*v.z + v.w*v.w;
    __shared__ float red[8];
    #pragma unroll
    for (int o = 16; o > 0; o >>= 1) ss += __shfl_xor_sync(0xffffffffu, ss, o);
    if ((t & 31) == 0) red[t >> 5] = ss;
    __syncthreads();
    if (t == 0) {
        float s = 0.f;
        #pragma unroll
        for (int i = 0; i < 8; i++) s += red[i];
        red[0] = s;
    }
    __syncthreads();
    float inv = rsqrtf(red[0]);
    v.x *= inv; v.y *= inv; v.z *= inv; v.w *= inv;
    ((float4*)dst)[t] = v;
    float4 r4;
    r4.x = tf32r(v.x); r4.y = tf32r(v.y); r4.z = tf32r(v.z); r4.w = tf32r(v.w);
    ((float4*)dstr)[t] = r4;
}

// ---------------- TF32 tensor-core NT GEMM (pre-rounded operands) ----------
// 3-stage cp.async pipeline.
// MODE 1: dual phase (Kd = 2F): k<F uses (A0,B0), k>=F uses (A1,B1), lda=F
// MODE 2: single (A0,B0)
// EPI 0: store raw            (SAGE h / approx sim)
// EPI 1: +bias, round tf32, also Am = max(aggp, x)   (intermediate proj)
// EPI 2: +bias, store raw to out                     (final proj)
template <int MODE, int EPI>
__global__ void __launch_bounds__(256, 2)
tgemm(const float* __restrict__ A0, const float* __restrict__ A1,
      const float* __restrict__ B0p, const float* __restrict__ B1p,
      const float* __restrict__ bias, const float* __restrict__ aggp,
      float* __restrict__ C, float* __restrict__ Am,
      int M, int N, int Kd) {
    const int BM = 128, BN = 128, BK = 16, NS = 3;
    __shared__ float As[NS][BM * BK];
    __shared__ float Bs[NS][BM * BK];

    const int tid  = threadIdx.x;
    const int lane = tid & 31;
    const int warp = tid >> 5;
    const int wm = warp >> 2;
    const int wn = warp & 3;
    const int g  = lane >> 3;
    const int li = lane & 7;
    const int m0 = blockIdx.y * BM;
    const int n0 = blockIdx.x * BN;

    const uint32_t sA = (uint32_t)__cvta_generic_to_shared(&As[0][0]);
    const uint32_t sB = (uint32_t)__cvta_generic_to_shared(&Bs[0][0]);

    float acc[4][4][4];
    #pragma unroll
    for (int a = 0; a < 4; a++)
        #pragma unroll
        for (int b = 0; b < 4; b++)
            #pragma unroll
            for (int c = 0; c < 4; c++) acc[a][b][c] = 0.f;

    const int halfK = Kd >> 1;
    const int NT = Kd / BK;

    auto issue_loads = [&](int kt) {
        int kk = kt * BK;
        int buf = kt % NS;
        const float* Aptr; const float* Bptr; int kb = kk; int ld;
        if (MODE == 1) {
            ld = halfK;
            if (kk >= halfK) { Aptr = A1; Bptr = B1p; kb = kk - halfK; }
            else             { Aptr = A0; Bptr = B0p; }
        } else {
            ld = Kd; Aptr = A0; Bptr = B0p;
        }
        #pragma unroll
        for (int it = 0; it < 2; it++) {
            int f = tid + it * 256;
            int r = f >> 2, c4 = f & 3;
            uint32_t soff = (uint32_t)(buf * BM * BK + r * BK + ((c4 ^ ((r >> 1) & 3)) << 2)) * 4u;
            cpasync16(sA + soff, Aptr + (size_t)(m0 + r) * ld + kb + c4 * 4);
            cpasync16(sB + soff, Bptr + (size_t)(n0 + r) * ld + kb + c4 * 4);
        }
        cp_commit();
    };

    issue_loads(0);
    issue_loads(1);

    for (int kt = 0; kt < NT; kt++) {
        if (kt + 1 < NT) cp_wait1(); else cp_wait0();
        __syncthreads();
        if (kt + 2 < NT) issue_loads(kt + 2);

        const uint32_t baseA = sA + (uint32_t)((kt % NS) * BM * BK) * 4u;
        const uint32_t baseB = sB + (uint32_t)((kt % NS) * BM * BK) * 4u;

        #pragma unroll
        for (int s = 0; s < 2; s++) {
            uint32_t a[4][4];
            #pragma unroll
            for (int mi = 0; mi < 4; mi++) {
                int row = wm * 64 + mi * 16 + ((g & 1) << 3) + li;
                int ch  = (2 * s + (g >> 1)) ^ ((row >> 1) & 3);
                ldsm4(a[mi][0], a[mi][1], a[mi][2], a[mi][3],
                      baseA + (uint32_t)((row * BK + (ch << 2)) << 2));
            }
            uint32_t b[4][2];
            #pragma unroll
            for (int p = 0; p < 2; p++) {
                int row = wn * 32 + p * 16 + ((g >> 1) << 3) + li;
                int ch  = (2 * s + (g & 1)) ^ ((row >> 1) & 3);
                uint32_t r0, r1, r2, r3;
                ldsm4(r0, r1, r2, r3,
                      baseB + (uint32_t)((row * BK + (ch << 2)) << 2));
                b[2*p][0] = r0; b[2*p][1] = r1;
                b[2*p+1][0] = r2; b[2*p+1][1] = r3;
            }
            #pragma unroll
            for (int mi = 0; mi < 4; mi++)
                #pragma unroll
                for (int nj = 0; nj < 4; nj++)
                    mma_tf32(acc[mi][nj], a[mi][0], a[mi][1], a[mi][2], a[mi][3],
                             b[nj][0], b[nj][1]);
        }
    }

    #pragma unroll
    for (int mi = 0; mi < 4; mi++) {
        #pragma unroll
        for (int half = 0; half < 2; half++) {
            int row = m0 + wm * 64 + mi * 16 + (lane >> 2) + half * 8;
            #pragma unroll
            for (int nj = 0; nj < 4; nj++) {
                int col = n0 + wn * 32 + nj * 8 + ((lane & 3) << 1);
                float v0 = acc[mi][nj][half * 2 + 0];
                float v1 = acc[mi][nj][half * 2 + 1];
                size_t idx = (size_t)row * N + col;
                if (EPI >= 1) { v0 += bias[col]; v1 += bias[col + 1]; }
                if (EPI == 1) {
                    v0 = tf32r(v0); v1 = tf32r(v1);
                    Am[idx]     = fmaxf(aggp[idx],     v0);
                    Am[idx + 1] = fmaxf(aggp[idx + 1], v1);
                }
                C[idx] = v0; C[idx + 1] = v1;
            }
        }
    }
}

// ---------------- top-16 candidates (approx) -> exact fp32 rescore -> top-8 -
// cached-local-max selection over smem (round-6 winner: 294 us measured)
__global__ void topk_kernel(float* __restrict__ out, int write_assign) {
    int b = blockIdx.x;
    int t = threadIdx.x;                      // 256 threads
    int lane = t & 31, w = t >> 5;
    __shared__ float sv[K_N];                 // approx sim row
    __shared__ float fnrow[F_N];              // exact fn row
    __shared__ float rv[8];
    __shared__ int   ri[8];
    __shared__ int   cand[NCAND];
    __shared__ float exacts[NCAND];

    const float* row = g_sim + (size_t)b * K_N;
    #pragma unroll
    for (int e = 0; e < K_N / 256; e++) sv[t + e * 256] = row[t + e * 256];
    {
        const float4* fr = (const float4*)(g_fn + (size_t)b * F_N);
        ((float4*)fnrow)[t] = fr[t];
    }
    __syncthreads();

    // cached per-thread local max over elements t, t+256, ..., t+1792
    float lmax = -3.0e38f; int lidx = 0;
    #pragma unroll
    for (int e = 0; e < K_N / 256; e++) {
        int i = t + e * 256;
        float v = sv[i];
        if (v > lmax) { lmax = v; lidx = i; }
    }

    for (int r = 0; r < NCAND; r++) {
        float bv = lmax; int bi = lidx;
        #pragma unroll
        for (int o = 16; o > 0; o >>= 1) {
            float ov = __shfl_xor_sync(0xffffffffu, bv, o);
            int   oi = __shfl_xor_sync(0xffffffffu, bi, o);
            if (ov > bv) { bv = ov; bi = oi; }
        }
        if (lane == 0) { rv[w] = bv; ri[w] = bi; }
        __syncthreads();
        if (t == 0) {
            float b2 = rv[0]; int i2 = ri[0];
            #pragma unroll
            for (int i = 1; i < 8; i++)
                if (rv[i] > b2) { b2 = rv[i]; i2 = ri[i]; }
            cand[r] = i2;
            sv[i2] = -3.0e38f;
        }
        __syncthreads();
        if ((cand[r] & 255) == t) {
            lmax = -3.0e38f; lidx = 0;
            #pragma unroll
            for (int e = 0; e < K_N / 256; e++) {
                int i = t + e * 256;
                float v = sv[i];
                if (v > lmax) { lmax = v; lidx = i; }
            }
        }
    }

    // exact fp32 rescore: warp w handles candidates 2w, 2w+1
    #pragma unroll
    for (int q = 0; q < 2; q++) {
        int c = w * 2 + q;
        const float* gp = g_gn + (size_t)cand[c] * F_N;
        float s = 0.f;
        #pragma unroll
        for (int e = 0; e < F_N / 32; e++)
            s = fmaf(fnrow[e * 32 + lane], gp[e * 32 + lane], s);
        #pragma unroll
        for (int o = 16; o > 0; o >>= 1) s += __shfl_xor_sync(0xffffffffu, s, o);
        if (lane == 0) exacts[c] = s;
    }
    __syncthreads();

    // top-8 of the 16 exact values (tie -> lower prototype index, matches jax)
    if (t == 0) {
        float ev[NCAND]; int ci[NCAND];
        #pragma unroll
        for (int i = 0; i < NCAND; i++) { ev[i] = exacts[i]; ci[i] = cand[i]; }
        #pragma unroll
        for (int r = 0; r < TOPK; r++) {
            int bj = 0;
            #pragma unroll
            for (int i = 1; i < NCAND; i++) {
                if (ev[i] > ev[bj] || (ev[i] == ev[bj] && ci[i] < ci[bj])) bj = i;
            }
            g_topk[b * TOPK + r] = ci[bj];
            if (r == 0 && write_assign) {
                #pragma unroll
                for (int dd = 0; dd < D_N; dd++)
                    out[(size_t)B_N * F_N + (size_t)dd * B_N + b] = (float)ci[bj];
            }
            ev[bj] = -3.0e38f;
        }
    }
}

// ---------------- aggp (tf32), x0 = tf32(features), am0 = max(aggp,x0) -----
__global__ void aggproto_kernel(const float* __restrict__ graphone,
                                const float* __restrict__ features) {
    int b = blockIdx.x;
    int t = threadIdx.x;
    __shared__ int idx[TOPK];
    if (t < TOPK) idx[t] = g_topk[b * TOPK + t];
    __syncthreads();
    float4 m = ((const float4*)(graphone + (size_t)idx[0] * F_N))[t];
    #pragma unroll
    for (int j = 1; j < TOPK; j++) {
        float4 v = ((const float4*)(graphone + (size_t)idx[j] * F_N))[t];
        m.x = fmaxf(m.x, v.x); m.y = fmaxf(m.y, v.y);
        m.z = fmaxf(m.z, v.z); m.w = fmaxf(m.w, v.w);
    }
    m.x = tf32r(m.x); m.y = tf32r(m.y); m.z = tf32r(m.z); m.w = tf32r(m.w);
    ((float4*)(g_aggp + (size_t)b * F_N))[t] = m;
    float4 f = ((const float4*)(features + (size_t)b * F_N))[t];
    f.x = tf32r(f.x); f.y = tf32r(f.y); f.z = tf32r(f.z); f.w = tf32r(f.w);
    ((float4*)(g_x + (size_t)b * F_N))[t] = f;
    float4 a;
    a.x = fmaxf(m.x, f.x); a.y = fmaxf(m.y, f.y);
    a.z = fmaxf(m.z, f.z); a.w = fmaxf(m.w, f.w);
    ((float4*)(g_am + (size_t)b * F_N))[t] = a;
}

// ---------------- tf32 rounding copy: all three weight tensors, one launch --
__global__ void convert_tf32_all(const float* __restrict__ W_l,
                                 const float* __restrict__ W_r,
                                 const float* __restrict__ W_p, int n4) {
    int i = blockIdx.x * blockDim.x + threadIdx.x;
    if (i >= 3 * n4) return;
    const float* src; float* dst; int j;
    if (i < n4)            { src = W_l; dst = g_wl; j = i; }
    else if (i < 2 * n4)   { src = W_r; dst = g_wr; j = i - n4; }
    else                   { src = W_p; dst = g_wp; j = i - 2 * n4; }
    float4 v = ((const float4*)src)[j];
    v.x = tf32r(v.x); v.y = tf32r(v.y); v.z = tf32r(v.z); v.w = tf32r(v.w);
    ((float4*)dst)[j] = v;
}

// ---------------- LayerNorm + ReLU + tf32 round, in place on g_h -----------
__global__ void ln_relu_kernel(const float* __restrict__ gamma,
                               const float* __restrict__ beta) {
    int b = blockIdx.x;
    int t = threadIdx.x;
    float* row = g_h + (size_t)b * H_N;
    float4 v = ((float4*)row)[t];
    float s  = v.x + v.y + v.z + v.w;
    float ss = v.x*v.x + v.y*v.y + v.z*v.z + v.w*v.w;
    __shared__ float r1[8], r2[8];
    #pragma unroll
    for (int o = 16; o > 0; o >>= 1) {
        s  += __shfl_xor_sync(0xffffffffu, s,  o);
        ss += __shfl_xor_sync(0xffffffffu, ss, o);
    }
    if ((t & 31) == 0) { r1[t >> 5] = s; r2[t >> 5] = ss; }
    __syncthreads();
    if (t == 0) {
        float a = 0.f, c = 0.f;
        #pragma unroll
        for (int i = 0; i < 8; i++) { a += r1[i]; c += r2[i]; }
        r1[0] = a; r2[0] = c;
    }
    __syncthreads();
    float mu  = r1[0] * (1.0f / H_N);
    float var = r2[0] * (1.0f / H_N) - mu * mu;
    float inv = rsqrtf(var + LN_EPS);
    float4 gm = ((const float4*)gamma)[t];
    float4 be = ((const float4*)beta)[t];
    v.x = tf32r(fmaxf((v.x - mu) * inv * gm.x + be.x, 0.f));
    v.y = tf32r(fmaxf((v.y - mu) * inv * gm.y + be.y, 0.f));
    v.z = tf32r(fmaxf((v.z - mu) * inv * gm.z + be.z, 0.f));
    v.w = tf32r(fmaxf((v.w - mu) * inv * gm.w + be.w, 0.f));
    ((float4*)row)[t] = v;
}

// ---------------------------------------------------------------------------
extern "C" void kernel_launch(void* const* d_in, const int* in_sizes, int n_in,
                              void* d_out, int out_size) {
    const float* features = (const float*)d_in[0];
    const float* graphone = (const float*)d_in[1];
    const float* W_l      = (const float*)d_in[2];
    const float* W_r      = (const float*)d_in[3];
    const float* gamma    = (const float*)d_in[4];
    const float* beta     = (const float*)d_in[5];
    const float* W_p      = (const float*)d_in[6];
    const float* b_p      = (const float*)d_in[7];
    float* out = (float*)d_out;

    float *fnr, *gnr, *sim, *aggp, *x, *h, *am, *wl, *wr, *wp;
    cudaGetSymbolAddress((void**)&fnr,  g_fnr);
    cudaGetSymbolAddress((void**)&gnr,  g_gnr);
    cudaGetSymbolAddress((void**)&sim,  g_sim);
    cudaGetSymbolAddress((void**)&aggp, g_aggp);
    cudaGetSymbolAddress((void**)&x,    g_x);
    cudaGetSymbolAddress((void**)&h,    g_h);
    cudaGetSymbolAddress((void**)&am,   g_am);
    cudaGetSymbolAddress((void**)&wl,   g_wl);
    cudaGetSymbolAddress((void**)&wr,   g_wr);
    cudaGetSymbolAddress((void**)&wp,   g_wp);

    // 0) tf32-round all weights (single launch)
    int nW = D_N * H_N * F_N / 4;
    convert_tf32_all<<<(3 * nW + 255) / 256, 256>>>(W_l, W_r, W_p, nW);

    // 1) row normalization -> exact (rescore) + tf32-rounded (approx sim)
    normalize_rows<<<B_N + K_N, 256>>>(features, graphone);

    // 2) APPROX sim = fnr @ gnr^T  (plain TF32 TC GEMM, no in-loop cvt)
    tgemm<2, 0><<<dim3(K_N / 128, B_N / 128), 256>>>(
        fnr, nullptr, gnr, nullptr, nullptr, nullptr, sim, nullptr,
        B_N, K_N, F_N);

    // 3) top-16 candidates -> exact rescore -> top-8 (+ assignments)
    long long need = (long long)B_N * F_N + (long long)D_N * B_N;
    int write_assign = ((long long)out_size >= need) ? 1 : 0;
    topk_kernel<<<B_N, 256>>>(out, write_assign);

    // 4) aggp (tf32), x0 = tf32(features), am0 = max(aggp, x0)
    aggproto_kernel<<<B_N, 256>>>(graphone, features);

    // 5) depth loop — tensor-core TF32 GEMMs
    for (int d = 0; d < D_N; d++) {
        // h = am @ W_l[d]^T + x @ W_r[d]^T  (dual-phase, Kd = 2F)
        tgemm<1, 0><<<dim3(H_N / 128, B_N / 128), 256>>>(
            am, x,
            wl + (size_t)d * H_N * F_N, wr + (size_t)d * H_N * F_N,
            nullptr, nullptr, h, nullptr, B_N, H_N, 2 * F_N);

        // LayerNorm + ReLU (+ tf32 rounding of h)
        ln_relu_kernel<<<B_N, 256>>>(gamma + (size_t)d * H_N,
                                     beta  + (size_t)d * H_N);

        if (d < D_N - 1) {
            // x = h @ W_p[d]^T + b_p ; also am = max(aggp, x) fused
            tgemm<2, 1><<<dim3(F_N / 128, B_N / 128), 256>>>(
                h, nullptr, wp + (size_t)d * F_N * H_N, nullptr,
                b_p + (size_t)d * F_N, aggp, x, am, B_N, F_N, H_N);
        } else {
            // final projection straight to d_out, full fp32 epilogue
            tgemm<2, 2><<<dim3(F_N / 128, B_N / 128), 256>>>(
                h, nullptr, wp + (size_t)d * F_N * H_N, nullptr,
                b_p + (size_t)d * F_N, nullptr, out, nullptr, B_N, F_N, H_N);
        }
    }
}

// round 9
// speedup vs baseline: 1.2142x; 1.1763x over previous
#include <cuda_runtime.h>
#include <cstdint>

#define B_N   16384
#define K_N   2048
#define F_N   1024
#define H_N   1024
#define D_N   3
#define TOPK  8
#define NCAND 16
#define LN_EPS 1e-5f

// ---------------- scratch (static device globals; no runtime allocation) ---
__device__ float g_fn  [(size_t)B_N * F_N];   // normalized features (fp32, exact)
__device__ float g_gn  [(size_t)K_N * F_N];   // normalized graphone (fp32, exact)
__device__ float g_fnr [(size_t)B_N * F_N];   // tf32-rounded fn (for approx sim)
__device__ float g_gnr [(size_t)K_N * F_N];   // tf32-rounded gn
__device__ float g_sim [(size_t)B_N * K_N];   // APPROX similarity (1xTF32)
__device__ int   g_topk[(size_t)B_N * TOPK];  // top-8 prototype idx per row
__device__ float g_aggp[(size_t)B_N * F_N];   // max over top-8 graphone rows (tf32)
__device__ float g_x   [(size_t)B_N * F_N];   // depth-loop activations (tf32)
__device__ float g_am  [(size_t)B_N * F_N];   // max(aggp, x) (tf32)
__device__ float g_h   [(size_t)B_N * H_N];   // hidden
__device__ float g_wl  [(size_t)D_N * H_N * F_N];  // tf32-rounded weights
__device__ float g_wr  [(size_t)D_N * H_N * F_N];
__device__ float g_wp  [(size_t)D_N * F_N * H_N];

// ---------------- small PTX helpers ----------------------------------------
__device__ __forceinline__ float tf32r(float x) {
    float r;
    asm("cvt.rna.tf32.f32 %0, %1;" : "=f"(r) : "f"(x));
    return r;
}
__device__ __forceinline__ void ldsm4(uint32_t& r0, uint32_t& r1,
                                      uint32_t& r2, uint32_t& r3, uint32_t a) {
    asm volatile("ldmatrix.sync.aligned.m8n8.x4.shared.b16 {%0,%1,%2,%3}, [%4];"
                 : "=r"(r0), "=r"(r1), "=r"(r2), "=r"(r3) : "r"(a));
}
__device__ __forceinline__ void mma_tf32(float c[4],
                                         uint32_t a0, uint32_t a1, uint32_t a2, uint32_t a3,
                                         uint32_t b0, uint32_t b1) {
    asm volatile("mma.sync.aligned.m16n8k8.row.col.f32.tf32.tf32.f32 "
                 "{%0,%1,%2,%3},{%4,%5,%6,%7},{%8,%9},{%0,%1,%2,%3};"
                 : "+f"(c[0]), "+f"(c[1]), "+f"(c[2]), "+f"(c[3])
                 : "r"(a0), "r"(a1), "r"(a2), "r"(a3), "r"(b0), "r"(b1));
}
__device__ __forceinline__ void cpasync16(uint32_t dst, const void* src) {
    asm volatile("cp.async.cg.shared.global [%0], [%1], 16;" :: "r"(dst), "l"(src));
}
__device__ __forceinline__ void cp_commit() {
    asm volatile("cp.async.commit_group;");
}
__device__ __forceinline__ void cp_wait0() {
    asm volatile("cp.async.wait_group 0;");
}
__device__ __forceinline__ void cp_wait1() {
    asm volatile("cp.async.wait_group 1;");
}

// ---------------- row L2 normalize; writes exact + tf32-rounded copies -----
__global__ void normalize_rows(const float* __restrict__ feat,
                               const float* __restrict__ gr) {
    int row = blockIdx.x;
    const float* src;
    float* dst; float* dstr;
    if (row < B_N) {
        src = feat + (size_t)row * F_N;
        dst = g_fn + (size_t)row * F_N;  dstr = g_fnr + (size_t)row * F_N;
    } else {
        row -= B_N;
        src = gr + (size_t)row * F_N;
        dst = g_gn + (size_t)row * F_N;  dstr = g_gnr + (size_t)row * F_N;
    }
    int t = threadIdx.x;
    float4 v = ((const float4*)src)[t];
    float ss = v.x*v.x + v.y*v.y + v.z*v.z + v.w*v.w;
    __shared__ float red[8];
    #pragma unroll
    for (int o = 16; o > 0; o >>= 1) ss += __shfl_xor_sync(0xffffffffu, ss, o);
    if ((t & 31) == 0) red[t >> 5] = ss;
    __syncthreads();
    if (t == 0) {
        float s = 0.f;
        #pragma unroll
        for (int i = 0; i < 8; i++) s += red[i];
        red[0] = s;
    }
    __syncthreads();
    float inv = rsqrtf(red[0]);
    v.x *= inv; v.y *= inv; v.z *= inv; v.w *= inv;
    ((float4*)dst)[t] = v;
    float4 r4;
    r4.x = tf32r(v.x); r4.y = tf32r(v.y); r4.z = tf32r(v.z); r4.w = tf32r(v.w);
    ((float4*)dstr)[t] = r4;
}

// ---------------- TF32 tensor-core NT GEMM, BK=32, 3-stage, dyn smem -------
// MODE 1: dual phase (Kd = 2F): k<F uses (A0,B0), k>=F uses (A1,B1), lda=F
// MODE 2: single (A0,B0)
// EPI 0: store raw   EPI 1: +bias,tf32,Am=max(aggp,x)   EPI 2: +bias -> out
template <int MODE, int EPI>
__global__ void __launch_bounds__(256, 2)
tgemm(const float* __restrict__ A0, const float* __restrict__ A1,
      const float* __restrict__ B0p, const float* __restrict__ B1p,
      const float* __restrict__ bias, const float* __restrict__ aggp,
      float* __restrict__ C, float* __restrict__ Am,
      int M, int N, int Kd) {
    const int BM = 128, BK = 32, NS = 3;
    const int STG = BM * BK;                  // floats per operand per stage
    extern __shared__ float smem[];
    float* As = smem;                         // NS*STG floats (48 KB)
    float* Bs = smem + NS * STG;              // NS*STG floats (48 KB)

    const int tid  = threadIdx.x;
    const int lane = tid & 31;
    const int warp = tid >> 5;
    const int wm = warp >> 2;
    const int wn = warp & 3;
    const int g  = lane >> 3;
    const int li = lane & 7;
    const int m0 = blockIdx.y * BM;
    const int n0 = blockIdx.x * BM;

    const uint32_t sA = (uint32_t)__cvta_generic_to_shared(As);
    const uint32_t sB = (uint32_t)__cvta_generic_to_shared(Bs);

    float acc[4][4][4];
    #pragma unroll
    for (int a = 0; a < 4; a++)
        #pragma unroll
        for (int b = 0; b < 4; b++)
            #pragma unroll
            for (int c = 0; c < 4; c++) acc[a][b][c] = 0.f;

    const int halfK = Kd >> 1;
    const int NT = Kd / BK;

    // SW128 swizzle over 8 16B-chunks per 128B row: chunk' = c8 ^ (row & 7)
    auto issue_loads = [&](int kt) {
        int kk = kt * BK;
        int buf = kt % NS;
        const float* Aptr; const float* Bptr; int kb = kk; int ld;
        if (MODE == 1) {
            ld = halfK;
            if (kk >= halfK) { Aptr = A1; Bptr = B1p; kb = kk - halfK; }
            else             { Aptr = A0; Bptr = B0p; }
        } else {
            ld = Kd; Aptr = A0; Bptr = B0p;
        }
        #pragma unroll
        for (int it = 0; it < 4; it++) {      // 1024 float4 per operand
            int f = tid + it * 256;
            int r = f >> 3, c8 = f & 7;
            uint32_t soff = (uint32_t)(buf * STG + r * BK + ((c8 ^ (r & 7)) << 2)) * 4u;
            cpasync16(sA + soff, Aptr + (size_t)(m0 + r) * ld + kb + c8 * 4);
            cpasync16(sB + soff, Bptr + (size_t)(n0 + r) * ld + kb + c8 * 4);
        }
        cp_commit();
    };

    issue_loads(0);
    issue_loads(1);

    for (int kt = 0; kt < NT; kt++) {
        if (kt + 1 < NT) cp_wait1(); else cp_wait0();
        __syncthreads();
        if (kt + 2 < NT) issue_loads(kt + 2);

        const uint32_t baseA = sA + (uint32_t)((kt % NS) * STG) * 4u;
        const uint32_t baseB = sB + (uint32_t)((kt % NS) * STG) * 4u;

        #pragma unroll
        for (int s = 0; s < 4; s++) {         // 4 k=8 slices per BK=32
            uint32_t a[4][4];
            #pragma unroll
            for (int mi = 0; mi < 4; mi++) {
                int row = wm * 64 + mi * 16 + ((g & 1) << 3) + li;
                int ch  = (2 * s + (g >> 1)) ^ (row & 7);
                ldsm4(a[mi][0], a[mi][1], a[mi][2], a[mi][3],
                      baseA + (uint32_t)((row * BK + (ch << 2)) << 2));
            }
            uint32_t b[4][2];
            #pragma unroll
            for (int p = 0; p < 2; p++) {
                int row = wn * 32 + p * 16 + ((g >> 1) << 3) + li;
                int ch  = (2 * s + (g & 1)) ^ (row & 7);
                uint32_t r0, r1, r2, r3;
                ldsm4(r0, r1, r2, r3,
                      baseB + (uint32_t)((row * BK + (ch << 2)) << 2));
                b[2*p][0] = r0; b[2*p][1] = r1;
                b[2*p+1][0] = r2; b[2*p+1][1] = r3;
            }
            #pragma unroll
            for (int mi = 0; mi < 4; mi++)
                #pragma unroll
                for (int nj = 0; nj < 4; nj++)
                    mma_tf32(acc[mi][nj], a[mi][0], a[mi][1], a[mi][2], a[mi][3],
                             b[nj][0], b[nj][1]);
        }
    }

    #pragma unroll
    for (int mi = 0; mi < 4; mi++) {
        #pragma unroll
        for (int half = 0; half < 2; half++) {
            int row = m0 + wm * 64 + mi * 16 + (lane >> 2) + half * 8;
            #pragma unroll
            for (int nj = 0; nj < 4; nj++) {
                int col = n0 + wn * 32 + nj * 8 + ((lane & 3) << 1);
                float v0 = acc[mi][nj][half * 2 + 0];
                float v1 = acc[mi][nj][half * 2 + 1];
                size_t idx = (size_t)row * N + col;
                if (EPI >= 1) { v0 += bias[col]; v1 += bias[col + 1]; }
                if (EPI == 1) {
                    v0 = tf32r(v0); v1 = tf32r(v1);
                    Am[idx]     = fmaxf(aggp[idx],     v0);
                    Am[idx + 1] = fmaxf(aggp[idx + 1], v1);
                }
                C[idx] = v0; C[idx + 1] = v1;
            }
        }
    }
}

// ---------------- warp-private topk: no block barriers ----------------------
// One row per warp (8 rows/block). Row lives in smem; selection state is
// warp-private (shfl only). Owner-lane invalidation + rescan of its 64 elems.
// Exact fp32 rescore of 16 candidates (fn/gn via L1/L2), top-8 matches jax.
__global__ void __launch_bounds__(256)
topk_kernel(float* __restrict__ out, int write_assign) {
    extern __shared__ float svall[];          // 8 * 2048 floats = 64 KB
    int t = threadIdx.x;
    int lane = t & 31, w = t >> 5;
    int b = blockIdx.x * 8 + w;
    float* svw = svall + w * K_N;

    __shared__ int   cands[8][NCAND];
    __shared__ float exacts[8][NCAND];

    // load row (coalesced float4), track per-lane local max over 64 elems
    const float* row = g_sim + (size_t)b * K_N;
    float lmax = -3.0e38f; int lidx = 0;
    #pragma unroll
    for (int e = 0; e < 16; e++) {
        int q = lane + e * 32;                // float4 slot
        float4 v = ((const float4*)row)[q];
        ((float4*)svw)[q] = v;
        int i0 = q * 4;
        if (v.x > lmax) { lmax = v.x; lidx = i0; }
        if (v.y > lmax) { lmax = v.y; lidx = i0 + 1; }
        if (v.z > lmax) { lmax = v.z; lidx = i0 + 2; }
        if (v.w > lmax) { lmax = v.w; lidx = i0 + 3; }
    }
    __syncwarp();

    // 16 selection rounds, warp-private
    for (int r = 0; r < NCAND; r++) {
        float bv = lmax; int bi = lidx;
        #pragma unroll
        for (int o = 16; o > 0; o >>= 1) {
            float ov = __shfl_xor_sync(0xffffffffu, bv, o);
            int   oi = __shfl_xor_sync(0xffffffffu, bi, o);
            if (ov > bv || (ov == bv && oi < bi)) { bv = ov; bi = oi; }
        }
        if (lane == 0) cands[w][r] = bi;
        // unique owner lane invalidates and rescans its 64 elements
        if (((bi >> 2) & 31) == lane) {
            svw[bi] = -3.0e38f;
            lmax = -3.0e38f; lidx = 0;
            #pragma unroll
            for (int e = 0; e < 16; e++) {
                int q = lane + e * 32;
                float4 v = ((const float4*)svw)[q];
                int i0 = q * 4;
                if (v.x > lmax) { lmax = v.x; lidx = i0; }
                if (v.y > lmax) { lmax = v.y; lidx = i0 + 1; }
                if (v.z > lmax) { lmax = v.z; lidx = i0 + 2; }
                if (v.w > lmax) { lmax = v.w; lidx = i0 + 3; }
            }
        }
        __syncwarp();
    }

    // exact fp32 rescore of the warp's 16 candidates
    const float* fp = g_fn + (size_t)b * F_N;
    for (int c = 0; c < NCAND; c++) {
        const float* gp = g_gn + (size_t)cands[w][c] * F_N;
        float s = 0.f;
        #pragma unroll
        for (int e = 0; e < F_N / 32; e++)
            s = fmaf(fp[e * 32 + lane], gp[e * 32 + lane], s);
        #pragma unroll
        for (int o = 16; o > 0; o >>= 1) s += __shfl_xor_sync(0xffffffffu, s, o);
        if (lane == 0) exacts[w][c] = s;
    }
    __syncwarp();

    // top-8 of 16 exact values (tie -> lower prototype index, matches jax)
    if (lane == 0) {
        #pragma unroll
        for (int r = 0; r < TOPK; r++) {
            int bj = 0;
            float bvv = exacts[w][0];
            #pragma unroll
            for (int i = 1; i < NCAND; i++) {
                float vi = exacts[w][i];
                if (vi > bvv || (vi == bvv && cands[w][i] < cands[w][bj])) {
                    bvv = vi; bj = i;
                }
            }
            g_topk[b * TOPK + r] = cands[w][bj];
            if (r == 0 && write_assign) {
                #pragma unroll
                for (int dd = 0; dd < D_N; dd++)
                    out[(size_t)B_N * F_N + (size_t)dd * B_N + b] = (float)cands[w][bj];
            }
            exacts[w][bj] = -3.0e38f;
        }
    }
}

// ---------------- aggp (tf32), x0 = tf32(features), am0 = max(aggp,x0) -----
__global__ void aggproto_kernel(const float* __restrict__ graphone,
                                const float* __restrict__ features) {
    int b = blockIdx.x;
    int t = threadIdx.x;
    __shared__ int idx[TOPK];
    if (t < TOPK) idx[t] = g_topk[b * TOPK + t];
    __syncthreads();
    float4 m = ((const float4*)(graphone + (size_t)idx[0] * F_N))[t];
    #pragma unroll
    for (int j = 1; j < TOPK; j++) {
        float4 v = ((const float4*)(graphone + (size_t)idx[j] * F_N))[t];
        m.x = fmaxf(m.x, v.x); m.y = fmaxf(m.y, v.y);
        m.z = fmaxf(m.z, v.z); m.w = fmaxf(m.w, v.w);
    }
    m.x = tf32r(m.x); m.y = tf32r(m.y); m.z = tf32r(m.z); m.w = tf32r(m.w);
    ((float4*)(g_aggp + (size_t)b * F_N))[t] = m;
    float4 f = ((const float4*)(features + (size_t)b * F_N))[t];
    f.x = tf32r(f.x); f.y = tf32r(f.y); f.z = tf32r(f.z); f.w = tf32r(f.w);
    ((float4*)(g_x + (size_t)b * F_N))[t] = f;
    float4 a;
    a.x = fmaxf(m.x, f.x); a.y = fmaxf(m.y, f.y);
    a.z = fmaxf(m.z, f.z); a.w = fmaxf(m.w, f.w);
    ((float4*)(g_am + (size_t)b * F_N))[t] = a;
}

// ---------------- tf32 rounding copy: all three weight tensors, one launch --
__global__ void convert_tf32_all(const float* __restrict__ W_l,
                                 const float* __restrict__ W_r,
                                 const float* __restrict__ W_p, int n4) {
    int i = blockIdx.x * blockDim.x + threadIdx.x;
    if (i >= 3 * n4) return;
    const float* src; float* dst; int j;
    if (i < n4)            { src = W_l; dst = g_wl; j = i; }
    else if (i < 2 * n4)   { src = W_r; dst = g_wr; j = i - n4; }
    else                   { src = W_p; dst = g_wp; j = i - 2 * n4; }
    float4 v = ((const float4*)src)[j];
    v.x = tf32r(v.x); v.y = tf32r(v.y); v.z = tf32r(v.z); v.w = tf32r(v.w);
    ((float4*)dst)[j] = v;
}

// ---------------- LayerNorm + ReLU + tf32 round, in place on g_h -----------
__global__ void ln_relu_kernel(const float* __restrict__ gamma,
                               const float* __restrict__ beta) {
    int b = blockIdx.x;
    int t = threadIdx.x;
    float* row = g_h + (size_t)b * H_N;
    float4 v = ((float4*)row)[t];
    float s  = v.x + v.y + v.z + v.w;
    float ss = v.x*v.x + v.y*v.y + v.z*v.z + v.w*v.w;
    __shared__ float r1[8], r2[8];
    #pragma unroll
    for (int o = 16; o > 0; o >>= 1) {
        s  += __shfl_xor_sync(0xffffffffu, s,  o);
        ss += __shfl_xor_sync(0xffffffffu, ss, o);
    }
    if ((t & 31) == 0) { r1[t >> 5] = s; r2[t >> 5] = ss; }
    __syncthreads();
    if (t == 0) {
        float a = 0.f, c = 0.f;
        #pragma unroll
        for (int i = 0; i < 8; i++) { a += r1[i]; c += r2[i]; }
        r1[0] = a; r2[0] = c;
    }
    __syncthreads();
    float mu  = r1[0] * (1.0f / H_N);
    float var = r2[0] * (1.0f / H_N) - mu * mu;
    float inv = rsqrtf(var + LN_EPS);
    float4 gm = ((const float4*)gamma)[t];
    float4 be = ((const float4*)beta)[t];
    v.x = tf32r(fmaxf((v.x - mu) * inv * gm.x + be.x, 0.f));
    v.y = tf32r(fmaxf((v.y - mu) * inv * gm.y + be.y, 0.f));
    v.z = tf32r(fmaxf((v.z - mu) * inv * gm.z + be.z, 0.f));
    v.w = tf32r(fmaxf((v.w - mu) * inv * gm.w + be.w, 0.f));
    ((float4*)row)[t] = v;
}

// ---------------------------------------------------------------------------
extern "C" void kernel_launch(void* const* d_in, const int* in_sizes, int n_in,
                              void* d_out, int out_size) {
    const float* features = (const float*)d_in[0];
    const float* graphone = (const float*)d_in[1];
    const float* W_l      = (const float*)d_in[2];
    const float* W_r      = (const float*)d_in[3];
    const float* gamma    = (const float*)d_in[4];
    const float* beta     = (const float*)d_in[5];
    const float* W_p      = (const float*)d_in[6];
    const float* b_p      = (const float*)d_in[7];
    float* out = (float*)d_out;

    float *fnr, *gnr, *sim, *aggp, *x, *h, *am, *wl, *wr, *wp;
    cudaGetSymbolAddress((void**)&fnr,  g_fnr);
    cudaGetSymbolAddress((void**)&gnr,  g_gnr);
    cudaGetSymbolAddress((void**)&sim,  g_sim);
    cudaGetSymbolAddress((void**)&aggp, g_aggp);
    cudaGetSymbolAddress((void**)&x,    g_x);
    cudaGetSymbolAddress((void**)&h,    g_h);
    cudaGetSymbolAddress((void**)&am,   g_am);
    cudaGetSymbolAddress((void**)&wl,   g_wl);
    cudaGetSymbolAddress((void**)&wr,   g_wr);
    cudaGetSymbolAddress((void**)&wp,   g_wp);

    const int GEMM_SMEM = 3 * 128 * 32 * 4 * 2;   // 96 KB (3-stage, A+B)
    const int TOPK_SMEM = 8 * K_N * 4;            // 64 KB
    cudaFuncSetAttribute(tgemm<2, 0>, cudaFuncAttributeMaxDynamicSharedMemorySize, GEMM_SMEM);
    cudaFuncSetAttribute(tgemm<1, 0>, cudaFuncAttributeMaxDynamicSharedMemorySize, GEMM_SMEM);
    cudaFuncSetAttribute(tgemm<2, 1>, cudaFuncAttributeMaxDynamicSharedMemorySize, GEMM_SMEM);
    cudaFuncSetAttribute(tgemm<2, 2>, cudaFuncAttributeMaxDynamicSharedMemorySize, GEMM_SMEM);
    cudaFuncSetAttribute(topk_kernel, cudaFuncAttributeMaxDynamicSharedMemorySize, TOPK_SMEM);

    // 0) tf32-round all weights (single launch)
    int nW = D_N * H_N * F_N / 4;
    convert_tf32_all<<<(3 * nW + 255) / 256, 256>>>(W_l, W_r, W_p, nW);

    // 1) row normalization -> exact (rescore) + tf32-rounded (approx sim)
    normalize_rows<<<B_N + K_N, 256>>>(features, graphone);

    // 2) APPROX sim = fnr @ gnr^T  (plain TF32 TC GEMM)
    tgemm<2, 0><<<dim3(K_N / 128, B_N / 128), 256, GEMM_SMEM>>>(
        fnr, nullptr, gnr, nullptr, nullptr, nullptr, sim, nullptr,
        B_N, K_N, F_N);

    // 3) warp-private top-16 -> exact rescore -> top-8 (+ assignments)
    long long need = (long long)B_N * F_N + (long long)D_N * B_N;
    int write_assign = ((long long)out_size >= need) ? 1 : 0;
    topk_kernel<<<B_N / 8, 256, TOPK_SMEM>>>(out, write_assign);

    // 4) aggp (tf32), x0 = tf32(features), am0 = max(aggp, x0)
    aggproto_kernel<<<B_N, 256>>>(graphone, features);

    // 5) depth loop — tensor-core TF32 GEMMs
    for (int d = 0; d < D_N; d++) {
        tgemm<1, 0><<<dim3(H_N / 128, B_N / 128), 256, GEMM_SMEM>>>(
            am, x,
            wl + (size_t)d * H_N * F_N, wr + (size_t)d * H_N * F_N,
            nullptr, nullptr, h, nullptr, B_N, H_N, 2 * F_N);

        ln_relu_kernel<<<B_N, 256>>>(gamma + (size_t)d * H_N,
                                     beta  + (size_t)d * H_N);

        if (d < D_N - 1) {
            tgemm<2, 1><<<dim3(F_N / 128, B_N / 128), 256, GEMM_SMEM>>>(
                h, nullptr, wp + (size_t)d * F_N * H_N, nullptr,
                b_p + (size_t)d * F_N, aggp, x, am, B_N, F_N, H_N);
        } else {
            tgemm<2, 2><<<dim3(F_N / 128, B_N / 128), 256, GEMM_SMEM>>>(
                h, nullptr, wp + (size_t)d * F_N * H_N, nullptr,
                b_p + (size_t)d * F_N, nullptr, out, nullptr, B_N, F_N, H_N);
        }
    }
}